// round 5
// baseline (speedup 1.0000x reference)
#include <cuda_runtime.h>
#include <cuda_fp16.h>
#include <math.h>
#include <stdint.h>

// ---------------- problem constants ----------------
#define N_ANG   256
#define DET_V   256
#define DET_U   384
#define VOL_N   128
#define D_SO    500.0f
#define D_SD    1000.0f
#define CU      191.5f
#define CV      127.5f
#define CC      63.5f
#define ROW_ELEMS (DET_V*DET_U)

// ---------------- device scratch ----------------
__device__ float2  g_h2[2*DET_U];                        // (hi,lo) tf32 split of ramp kernel, duplicated
__device__ float2  g_trig[N_ANG];                        // (cos, sin) per angle
__device__ __half2 g_filtH[(size_t)N_ANG*DET_V*DET_U];   // filtered proj, (p[u],p[u+1]) pairs

__device__ __forceinline__ float tf32_rna(float x) {
    uint32_t t;
    asm("cvt.rna.tf32.f32 %0, %1;" : "=r"(t) : "f"(x));
    return __uint_as_float(t);
}

// ---------------- kernel 0a: trig table ----------------
__global__ void prep_trig_kernel() {
    int a = threadIdx.x;
    double th = (double)a * (2.0 * M_PI / (double)N_ANG);
    g_trig[a] = make_float2((float)cos(th), (float)sin(th));
}

// ---------------- kernel 0b: h = irfft(ramp)*(pi/N_ANG), fp64 DFT + tf32 split ----------------
__global__ __launch_bounds__(192) void prep_h_kernel(const float* __restrict__ ramp) {
    __shared__ double swarp[6];
    int n = blockIdx.x;
    int k = threadIdx.x;

    double term;
    if (k == 0) {
        double nyq = (double)ramp[DET_U/2] * (((n & 1) == 0) ? 1.0 : -1.0);
        term = (double)ramp[0] + nyq;
    } else {
        int m = (k * n) % DET_U;
        term = 2.0 * (double)ramp[k] * cos(2.0 * M_PI * (double)m / (double)DET_U);
    }
    #pragma unroll
    for (int off = 16; off > 0; off >>= 1)
        term += __shfl_down_sync(0xffffffffu, term, off);
    if ((k & 31) == 0) swarp[k >> 5] = term;
    __syncthreads();
    if (k == 0) {
        double acc = 0.0;
        #pragma unroll
        for (int w = 0; w < 6; w++) acc += swarp[w];
        float h  = (float)(acc / (double)DET_U * (M_PI / (double)N_ANG));
        float hi = tf32_rna(h);
        float lo = tf32_rna(h - hi);
        float2 p = make_float2(hi, lo);
        g_h2[n] = p;
        g_h2[n + DET_U] = p;
    }
}

// ---------------- kernel 1: filter as 3xTF32 tensor-core GEMM (circulant B) ----------------
// block: 512 threads (16 warps), 64 rows (one angle quarter-group) x 384 outputs
// warp w: 4 m-tiles (16 rows) x 3 n-tiles (8 cols) at n0 = 24*w; K = 384 in 48 k8 steps
#define SS2 388    // float2 stride for S (==4 mod 16: conflict-free LDS.64 frags)
#define FILT_SMEM ((64*SS2 + 768) * 8)

__global__ __launch_bounds__(512) void filt_gemm_kernel(const float* __restrict__ proj,
                                                        const float* __restrict__ redund) {
    extern __shared__ float2 sm2[];
    float2* S2  = sm2;              // [64][SS2] (hi,lo)
    float2* sh2 = sm2 + 64 * SS2;   // [768]     (hi,lo)

    int tid  = threadIdx.x;
    int b    = blockIdx.x;
    int a    = b >> 2;
    int v0   = (b & 3) << 6;
    int row0 = b << 6;

    const float* prow = proj   + (size_t)row0 * DET_U;
    const float* rrow = redund + (size_t)a    * DET_U;

    // ---- fill S: weighted rows, tf32 hi/lo split ----
    for (int i = tid; i < 64 * DET_U; i += 512) {
        int r = i / DET_U;
        int c = i - r * DET_U;
        float vv = (float)(v0 + r) - CV;
        float uu = (float)c - CU;
        float cw = D_SD * rsqrtf(D_SD*D_SD + vv*vv + uu*uu);
        float val = prow[i] * cw * rrow[c];
        float hi = tf32_rna(val);
        float lo = tf32_rna(val - hi);
        S2[r * SS2 + c] = make_float2(hi, lo);
    }
    for (int i = tid; i < 2 * DET_U; i += 512) sh2[i] = g_h2[i];
    __syncthreads();

    int w    = tid >> 5;
    int lane = tid & 31;
    int gr   = lane >> 2;
    int tig  = lane & 3;
    int n0   = w * 24;

    float acc[4][3][4];
    #pragma unroll
    for (int mt = 0; mt < 4; mt++)
        #pragma unroll
        for (int nt = 0; nt < 3; nt++)
            #pragma unroll
            for (int q = 0; q < 4; q++) acc[mt][nt][q] = 0.f;

    const float2* Sb = S2 + gr * SS2 + tig;
    int bC = n0 + gr - tig + DET_U;       // B index base: sh2[bC + nt*8 - kg]

    #pragma unroll 4
    for (int ksg = 0; ksg < 48; ksg++) {
        int kg = ksg * 8;
        float2 A[4][4];
        #pragma unroll
        for (int mt = 0; mt < 4; mt++) {
            const float2* Ap = Sb + mt * (16 * SS2) + kg;
            A[mt][0] = Ap[0];
            A[mt][1] = Ap[8 * SS2];
            A[mt][2] = Ap[4];
            A[mt][3] = Ap[8 * SS2 + 4];
        }
        #pragma unroll
        for (int nt = 0; nt < 3; nt++) {
            int bi = bC + nt * 8 - kg;
            float2 b0 = sh2[bi];          // k = kg+tig
            float2 b1 = sh2[bi - 4];      // k = kg+tig+4
            #pragma unroll
            for (int mt = 0; mt < 4; mt++) {
                // hi*hi
                asm volatile(
                    "mma.sync.aligned.m16n8k8.row.col.f32.tf32.tf32.f32 "
                    "{%0,%1,%2,%3}, {%4,%5,%6,%7}, {%8,%9}, {%0,%1,%2,%3};"
                    : "+f"(acc[mt][nt][0]), "+f"(acc[mt][nt][1]),
                      "+f"(acc[mt][nt][2]), "+f"(acc[mt][nt][3])
                    : "r"(__float_as_uint(A[mt][0].x)), "r"(__float_as_uint(A[mt][1].x)),
                      "r"(__float_as_uint(A[mt][2].x)), "r"(__float_as_uint(A[mt][3].x)),
                      "r"(__float_as_uint(b0.x)), "r"(__float_as_uint(b1.x)));
                // hi*lo
                asm volatile(
                    "mma.sync.aligned.m16n8k8.row.col.f32.tf32.tf32.f32 "
                    "{%0,%1,%2,%3}, {%4,%5,%6,%7}, {%8,%9}, {%0,%1,%2,%3};"
                    : "+f"(acc[mt][nt][0]), "+f"(acc[mt][nt][1]),
                      "+f"(acc[mt][nt][2]), "+f"(acc[mt][nt][3])
                    : "r"(__float_as_uint(A[mt][0].x)), "r"(__float_as_uint(A[mt][1].x)),
                      "r"(__float_as_uint(A[mt][2].x)), "r"(__float_as_uint(A[mt][3].x)),
                      "r"(__float_as_uint(b0.y)), "r"(__float_as_uint(b1.y)));
                // lo*hi
                asm volatile(
                    "mma.sync.aligned.m16n8k8.row.col.f32.tf32.tf32.f32 "
                    "{%0,%1,%2,%3}, {%4,%5,%6,%7}, {%8,%9}, {%0,%1,%2,%3};"
                    : "+f"(acc[mt][nt][0]), "+f"(acc[mt][nt][1]),
                      "+f"(acc[mt][nt][2]), "+f"(acc[mt][nt][3])
                    : "r"(__float_as_uint(A[mt][0].y)), "r"(__float_as_uint(A[mt][1].y)),
                      "r"(__float_as_uint(A[mt][2].y)), "r"(__float_as_uint(A[mt][3].y)),
                      "r"(__float_as_uint(b0.x)), "r"(__float_as_uint(b1.x)));
            }
        }
    }

    // ---- epilogue: stage fp32 results, pack (p[u],p[u+1]) half2 pairs ----
    __syncthreads();
    float* Sf = reinterpret_cast<float*>(sm2);    // reuse as [64][388] floats
    #pragma unroll
    for (int mt = 0; mt < 4; mt++) {
        int r = 16 * mt + gr;
        #pragma unroll
        for (int nt = 0; nt < 3; nt++) {
            int col = n0 + nt * 8 + 2 * tig;
            *reinterpret_cast<float2*>(&Sf[r * 388 + col])       = make_float2(acc[mt][nt][0], acc[mt][nt][1]);
            *reinterpret_cast<float2*>(&Sf[(r + 8) * 388 + col]) = make_float2(acc[mt][nt][2], acc[mt][nt][3]);
        }
    }
    __syncthreads();

    for (int i = tid; i < 64 * 96; i += 512) {
        int r  = i / 96;
        int c4 = (i - r * 96) * 4;
        const float* Sp = &Sf[r * 388 + c4];
        float o0 = Sp[0], o1 = Sp[1], o2 = Sp[2], o3 = Sp[3];
        float o4 = (c4 == DET_U - 4) ? 0.0f : Sp[4];
        __half2 h0 = __floats2half2_rn(o0, o1);
        __half2 h1 = __floats2half2_rn(o1, o2);
        __half2 h2 = __floats2half2_rn(o2, o3);
        __half2 h3 = __floats2half2_rn(o3, o4);
        uint4 pack;
        pack.x = *reinterpret_cast<unsigned int*>(&h0);
        pack.y = *reinterpret_cast<unsigned int*>(&h1);
        pack.z = *reinterpret_cast<unsigned int*>(&h2);
        pack.w = *reinterpret_cast<unsigned int*>(&h3);
        *reinterpret_cast<uint4*>(g_filtH + (size_t)(row0 + r) * DET_U + c4) = pack;
    }
}

// ---------------- kernel 2: backprojection (half2 u-pair loads) ----------------
#define ZPT 16
__global__ __launch_bounds__(128) void bp_kernel(float* __restrict__ out) {
    __shared__ float2 strig[N_ANG];
    int tid = threadIdx.x;
    for (int i = tid; i < N_ANG; i += 128) strig[i] = g_trig[i];
    __syncthreads();

    int x  = tid;
    int y  = blockIdx.x;
    int z0 = blockIdx.y * ZPT;

    float xc  = (float)x  - CC;
    float yc  = (float)y  - CC;
    float zc0 = (float)z0 - CC;

    float acc[ZPT];
    #pragma unroll
    for (int j = 0; j < ZPT; j++) acc[j] = 0.f;

    for (int aIdx = 0; aIdx < N_ANG; aIdx++) {
        float2 cs = strig[aIdx];
        float c = cs.x, s = cs.y;
        float t = yc * c - xc * s;
        float r = D_SO - (xc * c + yc * s);
        float rinv = __fdividef(1.0f, r);

        float iu  = fmaf(D_SD * t, rinv, CU);
        int   u0r = __float2int_rd(iu);
        float fu  = iu - __int2float_rn(u0r);
        float wq  = D_SO * rinv;
        float w   = ((unsigned)u0r < (unsigned)(DET_U - 1)) ? wq * wq : 0.0f;
        int   u0i = min(max(u0r, 0), DET_U - 2);

        float kz  = D_SD * rinv;
        float iv0 = fmaf(kz, zc0, CV);

        const __half2* base = g_filtH + (size_t)aIdx * ROW_ELEMS + u0i;

        #pragma unroll
        for (int j = 0; j < ZPT; j++) {
            float iv  = fmaf(kz, (float)j, iv0);   // independent per-j FMA (no serial chain)
            int   v0r = __float2int_rd(iv);
            float fv  = iv - __int2float_rn(v0r);
            float wz  = ((unsigned)v0r < (unsigned)(DET_V - 1)) ? w : 0.0f;
            int   v0i = min(max(v0r, 0), DET_V - 2);
            const __half2* p = base + v0i * DET_U;
            float2 f0 = __half22float2(p[0]);
            float2 f1 = __half22float2(p[DET_U]);
            float aa  = fmaf(fu, f0.y - f0.x, f0.x);
            float bb  = fmaf(fu, f1.y - f1.x, f1.x);
            float val = fmaf(fv, bb - aa, aa);
            acc[j] = fmaf(val, wz, acc[j]);
        }
    }

    size_t obase = ((size_t)z0 * VOL_N + y) * VOL_N + x;
    #pragma unroll
    for (int j = 0; j < ZPT; j++) {
        out[obase + (size_t)j * VOL_N * VOL_N] = acc[j];
    }
}

// ---------------- launch ----------------
extern "C" void kernel_launch(void* const* d_in, const int* in_sizes, int n_in,
                              void* d_out, int out_size) {
    const float* proj   = nullptr;
    const float* ramp   = nullptr;
    const float* redund = nullptr;
    for (int i = 0; i < n_in; i++) {
        if (in_sizes[i] == DET_U/2 + 1)                    ramp   = (const float*)d_in[i];
        else if (in_sizes[i] == N_ANG * DET_U)             redund = (const float*)d_in[i];
        else if (in_sizes[i] == N_ANG * DET_V * DET_U)     proj   = (const float*)d_in[i];
    }

    cudaFuncSetAttribute(filt_gemm_kernel,
                         cudaFuncAttributeMaxDynamicSharedMemorySize, FILT_SMEM);

    prep_trig_kernel<<<1, N_ANG>>>();
    prep_h_kernel<<<DET_U, 192>>>(ramp);
    filt_gemm_kernel<<<(N_ANG*DET_V)/64, 512, FILT_SMEM>>>(proj, redund);
    dim3 grid(VOL_N, VOL_N / ZPT);
    bp_kernel<<<grid, 128>>>((float*)d_out);
}

// round 6
// speedup vs baseline: 1.2147x; 1.2147x over previous
#include <cuda_runtime.h>
#include <cuda_fp16.h>
#include <math.h>
#include <stdint.h>

// ---------------- problem constants ----------------
#define N_ANG   256
#define DET_V   256
#define DET_U   384
#define VOL_N   128
#define D_SO    500.0f
#define D_SD    1000.0f
#define CU      191.5f
#define CV      127.5f
#define CC      63.5f
#define ROW_ELEMS (DET_V*DET_U)

// quad buffer geometry
#define QS_U    392                 // uint2 quads per row (cols 0..391; used 0..385)
#define QS_ROWS 257                 // rows v' = v0+1 in [0,256]
#define QS_ANG  (QS_U*QS_ROWS)      // 100744 quads per angle

// ---------------- device scratch ----------------
__device__ float2  g_h2[2*DET_U];                        // (hi,lo) tf32 split of ramp kernel
__device__ float2  g_trig[N_ANG];                        // (cos, sin) per angle
__device__ __half2 g_filtH[(size_t)N_ANG*DET_V*DET_U];   // filtered proj, (p[u],p[u+1]) pairs (100MB)
__device__ uint4   g_filtQ4[(size_t)N_ANG*QS_ANG/2];     // padded bilinear quads (197MB)

__device__ __forceinline__ float tf32_rna(float x) {
    uint32_t t;
    asm("cvt.rna.tf32.f32 %0, %1;" : "=r"(t) : "f"(x));
    return __uint_as_float(t);
}

// ---------------- kernel 0a: trig table ----------------
__global__ void prep_trig_kernel() {
    int a = threadIdx.x;
    double th = (double)a * (2.0 * M_PI / (double)N_ANG);
    g_trig[a] = make_float2((float)cos(th), (float)sin(th));
}

// ---------------- kernel 0b: h = irfft(ramp)*(pi/N_ANG), fp64 DFT + tf32 split ----------------
__global__ __launch_bounds__(192) void prep_h_kernel(const float* __restrict__ ramp) {
    __shared__ double swarp[6];
    int n = blockIdx.x;
    int k = threadIdx.x;

    double term;
    if (k == 0) {
        double nyq = (double)ramp[DET_U/2] * (((n & 1) == 0) ? 1.0 : -1.0);
        term = (double)ramp[0] + nyq;
    } else {
        int m = (k * n) % DET_U;
        term = 2.0 * (double)ramp[k] * cos(2.0 * M_PI * (double)m / (double)DET_U);
    }
    #pragma unroll
    for (int off = 16; off > 0; off >>= 1)
        term += __shfl_down_sync(0xffffffffu, term, off);
    if ((k & 31) == 0) swarp[k >> 5] = term;
    __syncthreads();
    if (k == 0) {
        double acc = 0.0;
        #pragma unroll
        for (int w = 0; w < 6; w++) acc += swarp[w];
        float h  = (float)(acc / (double)DET_U * (M_PI / (double)N_ANG));
        float hi = tf32_rna(h);
        float lo = tf32_rna(h - hi);
        float2 p = make_float2(hi, lo);
        g_h2[n] = p;
        g_h2[n + DET_U] = p;
    }
}

// ---------------- kernel 1: filter as 3xTF32 tensor-core GEMM (circulant B) ----------------
#define SS2 388
#define FILT_SMEM ((64*SS2 + 768) * 8)

__global__ __launch_bounds__(512) void filt_gemm_kernel(const float* __restrict__ proj,
                                                        const float* __restrict__ redund) {
    extern __shared__ float2 sm2[];
    float2* S2  = sm2;
    float2* sh2 = sm2 + 64 * SS2;

    int tid  = threadIdx.x;
    int b    = blockIdx.x;
    int a    = b >> 2;
    int v0   = (b & 3) << 6;
    int row0 = b << 6;

    const float* prow = proj   + (size_t)row0 * DET_U;
    const float* rrow = redund + (size_t)a    * DET_U;

    for (int i = tid; i < 64 * DET_U; i += 512) {
        int r = i / DET_U;
        int c = i - r * DET_U;
        float vv = (float)(v0 + r) - CV;
        float uu = (float)c - CU;
        float cw = D_SD * rsqrtf(D_SD*D_SD + vv*vv + uu*uu);
        float val = prow[i] * cw * rrow[c];
        float hi = tf32_rna(val);
        float lo = tf32_rna(val - hi);
        S2[r * SS2 + c] = make_float2(hi, lo);
    }
    for (int i = tid; i < 2 * DET_U; i += 512) sh2[i] = g_h2[i];
    __syncthreads();

    int w    = tid >> 5;
    int lane = tid & 31;
    int gr   = lane >> 2;
    int tig  = lane & 3;
    int n0   = w * 24;

    float acc[4][3][4];
    #pragma unroll
    for (int mt = 0; mt < 4; mt++)
        #pragma unroll
        for (int nt = 0; nt < 3; nt++)
            #pragma unroll
            for (int q = 0; q < 4; q++) acc[mt][nt][q] = 0.f;

    const float2* Sb = S2 + gr * SS2 + tig;
    int bC = n0 + gr - tig + DET_U;

    #pragma unroll 4
    for (int ksg = 0; ksg < 48; ksg++) {
        int kg = ksg * 8;
        float2 A[4][4];
        #pragma unroll
        for (int mt = 0; mt < 4; mt++) {
            const float2* Ap = Sb + mt * (16 * SS2) + kg;
            A[mt][0] = Ap[0];
            A[mt][1] = Ap[8 * SS2];
            A[mt][2] = Ap[4];
            A[mt][3] = Ap[8 * SS2 + 4];
        }
        #pragma unroll
        for (int nt = 0; nt < 3; nt++) {
            int bi = bC + nt * 8 - kg;
            float2 b0 = sh2[bi];
            float2 b1 = sh2[bi - 4];
            #pragma unroll
            for (int mt = 0; mt < 4; mt++) {
                asm volatile(
                    "mma.sync.aligned.m16n8k8.row.col.f32.tf32.tf32.f32 "
                    "{%0,%1,%2,%3}, {%4,%5,%6,%7}, {%8,%9}, {%0,%1,%2,%3};"
                    : "+f"(acc[mt][nt][0]), "+f"(acc[mt][nt][1]),
                      "+f"(acc[mt][nt][2]), "+f"(acc[mt][nt][3])
                    : "r"(__float_as_uint(A[mt][0].x)), "r"(__float_as_uint(A[mt][1].x)),
                      "r"(__float_as_uint(A[mt][2].x)), "r"(__float_as_uint(A[mt][3].x)),
                      "r"(__float_as_uint(b0.x)), "r"(__float_as_uint(b1.x)));
                asm volatile(
                    "mma.sync.aligned.m16n8k8.row.col.f32.tf32.tf32.f32 "
                    "{%0,%1,%2,%3}, {%4,%5,%6,%7}, {%8,%9}, {%0,%1,%2,%3};"
                    : "+f"(acc[mt][nt][0]), "+f"(acc[mt][nt][1]),
                      "+f"(acc[mt][nt][2]), "+f"(acc[mt][nt][3])
                    : "r"(__float_as_uint(A[mt][0].x)), "r"(__float_as_uint(A[mt][1].x)),
                      "r"(__float_as_uint(A[mt][2].x)), "r"(__float_as_uint(A[mt][3].x)),
                      "r"(__float_as_uint(b0.y)), "r"(__float_as_uint(b1.y)));
                asm volatile(
                    "mma.sync.aligned.m16n8k8.row.col.f32.tf32.tf32.f32 "
                    "{%0,%1,%2,%3}, {%4,%5,%6,%7}, {%8,%9}, {%0,%1,%2,%3};"
                    : "+f"(acc[mt][nt][0]), "+f"(acc[mt][nt][1]),
                      "+f"(acc[mt][nt][2]), "+f"(acc[mt][nt][3])
                    : "r"(__float_as_uint(A[mt][0].y)), "r"(__float_as_uint(A[mt][1].y)),
                      "r"(__float_as_uint(A[mt][2].y)), "r"(__float_as_uint(A[mt][3].y)),
                      "r"(__float_as_uint(b0.x)), "r"(__float_as_uint(b1.x)));
            }
        }
    }

    __syncthreads();
    float* Sf = reinterpret_cast<float*>(sm2);
    #pragma unroll
    for (int mt = 0; mt < 4; mt++) {
        int r = 16 * mt + gr;
        #pragma unroll
        for (int nt = 0; nt < 3; nt++) {
            int col = n0 + nt * 8 + 2 * tig;
            *reinterpret_cast<float2*>(&Sf[r * 388 + col])       = make_float2(acc[mt][nt][0], acc[mt][nt][1]);
            *reinterpret_cast<float2*>(&Sf[(r + 8) * 388 + col]) = make_float2(acc[mt][nt][2], acc[mt][nt][3]);
        }
    }
    __syncthreads();

    for (int i = tid; i < 64 * 96; i += 512) {
        int r  = i / 96;
        int c4 = (i - r * 96) * 4;
        const float* Sp = &Sf[r * 388 + c4];
        float o0 = Sp[0], o1 = Sp[1], o2 = Sp[2], o3 = Sp[3];
        float o4 = (c4 == DET_U - 4) ? 0.0f : Sp[4];
        __half2 h0 = __floats2half2_rn(o0, o1);
        __half2 h1 = __floats2half2_rn(o1, o2);
        __half2 h2 = __floats2half2_rn(o2, o3);
        __half2 h3 = __floats2half2_rn(o3, o4);
        uint4 pack;
        pack.x = *reinterpret_cast<unsigned int*>(&h0);
        pack.y = *reinterpret_cast<unsigned int*>(&h1);
        pack.z = *reinterpret_cast<unsigned int*>(&h2);
        pack.w = *reinterpret_cast<unsigned int*>(&h3);
        *reinterpret_cast<uint4*>(g_filtH + (size_t)(row0 + r) * DET_U + c4) = pack;
    }
}

// ---------------- kernel 1b: build padded bilinear quads ----------------
// Q[a][v0+1][u0+2] = (p00,p10 | p01,p11), transposed for HFMA2 u-lerp.
// Border rows/cols (u0 or v0 out of the reference validity range) are zero quads.
__global__ __launch_bounds__(256) void requad_kernel() {
    int j  = threadIdx.x;          // 0..255, active 0..192 (two cols each)
    if (j > 192) return;
    int vp = blockIdx.x;           // 0..256  (= v0+1)
    int a  = blockIdx.y;           // 0..255

    int c0 = 2 * j;                // cols c0, c0+1  (<= 385)
    uint4 outv = make_uint4(0u, 0u, 0u, 0u);

    bool rowok = (vp >= 1) && (vp <= 255);
    if (rowok && j >= 1) {
        int u0 = c0 - 2;           // 0..382, even
        const __half2* Hrow = g_filtH + (size_t)a * ROW_ELEMS + (size_t)(vp - 1) * DET_U + u0;
        uint2 top = *reinterpret_cast<const uint2*>(Hrow);           // (p00,p01)@u0, @u0+1
        uint2 bot = *reinterpret_cast<const uint2*>(Hrow + DET_U);   // (p10,p11)@u0, @u0+1

        __half2 A0 = *reinterpret_cast<__half2*>(&top.x);
        __half2 B0 = *reinterpret_cast<__half2*>(&bot.x);
        __half2 lo0 = __lows2half2(A0, B0);    // (p00, p10)
        __half2 hi0 = __highs2half2(A0, B0);   // (p01, p11)
        outv.x = *reinterpret_cast<unsigned int*>(&lo0);
        outv.y = *reinterpret_cast<unsigned int*>(&hi0);

        if (j <= 191) {                        // col c0+1 -> u' = c0, u0' = c0-1 <= 382
            __half2 A1 = *reinterpret_cast<__half2*>(&top.y);
            __half2 B1 = *reinterpret_cast<__half2*>(&bot.y);
            __half2 lo1 = __lows2half2(A1, B1);
            __half2 hi1 = __highs2half2(A1, B1);
            outv.z = *reinterpret_cast<unsigned int*>(&lo1);
            outv.w = *reinterpret_cast<unsigned int*>(&hi1);
        }
    }

    size_t qidx = ((size_t)a * QS_ANG + (size_t)vp * QS_U + c0) >> 1;   // uint4 units
    g_filtQ4[qidx] = outv;
}

// ---------------- kernel 2: backprojection (single LDG.64 quad, clamp-only) ----------------
#define ZPT 8
__global__ __launch_bounds__(128) void bp_kernel(float* __restrict__ out) {
    __shared__ float2 strig[N_ANG];
    int tid = threadIdx.x;
    for (int i = tid; i < N_ANG; i += 128) strig[i] = g_trig[i];
    __syncthreads();

    int x  = tid;
    int y  = blockIdx.x;
    int z0 = blockIdx.y * ZPT;

    float xc  = (float)x  - CC;
    float yc  = (float)y  - CC;
    float zc0 = (float)z0 - CC;

    float acc[ZPT];
    #pragma unroll
    for (int j = 0; j < ZPT; j++) acc[j] = 0.f;

    const uint2* Q = reinterpret_cast<const uint2*>(g_filtQ4);

    #pragma unroll 2
    for (int aIdx = 0; aIdx < N_ANG; aIdx++) {
        float2 cs = strig[aIdx];
        float c = cs.x, s = cs.y;
        float t = yc * c - xc * s;
        float r = D_SO - (xc * c + yc * s);
        float rinv = __fdividef(1.0f, r);

        float iu  = fmaf(D_SD * t, rinv, CU);
        int   u0r = __float2int_rd(iu);
        float fu  = iu - __int2float_rn(u0r);
        int   u0i = min(max(u0r, -1), DET_U - 1);   // [-1,383] -> zero-quad borders
        __half2 fu2 = __float2half2_rn(fu);

        float wq = D_SO * rinv;
        float w  = wq * wq;

        float kz  = D_SD * rinv;
        float iv0 = fmaf(kz, zc0, CV);

        const uint2* rowp = Q + (size_t)aIdx * QS_ANG + (QS_U + 2) + u0i;

        #pragma unroll
        for (int j = 0; j < ZPT; j++) {
            float iv  = fmaf(kz, (float)j, iv0);
            int   v0r = __float2int_rd(iv);
            float fv  = iv - __int2float_rn(v0r);
            int   v0i = min(max(v0r, -1), DET_V - 1);   // [-1,255]
            uint2 q = rowp[(size_t)v0i * QS_U];
            __half2 A = *reinterpret_cast<__half2*>(&q.x);   // (p00, p10)
            __half2 B = *reinterpret_cast<__half2*>(&q.y);   // (p01, p11)
            __half2 E = __hfma2(fu2, __hsub2(B, A), A);      // (aa, bb)
            float2 e = __half22float2(E);
            float val = fmaf(fv, e.y - e.x, e.x);
            acc[j] = fmaf(val, w, acc[j]);
        }
    }

    size_t obase = ((size_t)z0 * VOL_N + y) * VOL_N + x;
    #pragma unroll
    for (int j = 0; j < ZPT; j++) {
        out[obase + (size_t)j * VOL_N * VOL_N] = acc[j];
    }
}

// ---------------- launch ----------------
extern "C" void kernel_launch(void* const* d_in, const int* in_sizes, int n_in,
                              void* d_out, int out_size) {
    const float* proj   = nullptr;
    const float* ramp   = nullptr;
    const float* redund = nullptr;
    for (int i = 0; i < n_in; i++) {
        if (in_sizes[i] == DET_U/2 + 1)                    ramp   = (const float*)d_in[i];
        else if (in_sizes[i] == N_ANG * DET_U)             redund = (const float*)d_in[i];
        else if (in_sizes[i] == N_ANG * DET_V * DET_U)     proj   = (const float*)d_in[i];
    }

    cudaFuncSetAttribute(filt_gemm_kernel,
                         cudaFuncAttributeMaxDynamicSharedMemorySize, FILT_SMEM);

    prep_trig_kernel<<<1, N_ANG>>>();
    prep_h_kernel<<<DET_U, 192>>>(ramp);
    filt_gemm_kernel<<<(N_ANG*DET_V)/64, 512, FILT_SMEM>>>(proj, redund);
    dim3 qgrid(QS_ROWS, N_ANG);
    requad_kernel<<<qgrid, 256>>>();
    dim3 grid(VOL_N, VOL_N / ZPT);
    bp_kernel<<<grid, 128>>>((float*)d_out);
}

// round 7
// speedup vs baseline: 1.3399x; 1.1031x over previous
#include <cuda_runtime.h>
#include <cuda_fp16.h>
#include <math.h>
#include <stdint.h>

// ---------------- problem constants ----------------
#define N_ANG   256
#define DET_V   256
#define DET_U   384
#define VOL_N   128
#define D_SO    500.0f
#define D_SD    1000.0f
#define CU      191.5f
#define CV      127.5f
#define CC      63.5f
#define ROW_ELEMS (DET_V*DET_U)
#define VOL_ELEMS (VOL_N*VOL_N*VOL_N)

// quad buffer geometry
#define QS_U    392                 // uint2 quads per row (cols 0..391; used 0..385)
#define QS_ROWS 257                 // rows v' = v0+1 in [0,256]
#define QS_ANG  (QS_U*QS_ROWS)      // quads per angle

// angle split for BP occupancy
#define ASPLIT  4
#define ACHUNK  (N_ANG/ASPLIT)      // 64

// ---------------- device scratch ----------------
__device__ float2  g_h2[2*DET_U];                        // (hi,lo) tf32 split of ramp kernel
__device__ float2  g_trig[N_ANG];                        // (cos, sin) per angle
__device__ __half2 g_filtH[(size_t)N_ANG*DET_V*DET_U];   // filtered proj, (p[u],p[u+1]) pairs
__device__ uint4   g_filtQ4[(size_t)N_ANG*QS_ANG/2];     // padded bilinear quads
__device__ float   g_part[(size_t)ASPLIT*VOL_ELEMS];     // partial volumes (33.5MB)

__device__ __forceinline__ float tf32_rna(float x) {
    uint32_t t;
    asm("cvt.rna.tf32.f32 %0, %1;" : "=r"(t) : "f"(x));
    return __uint_as_float(t);
}

// ---------------- kernel 0a: trig table ----------------
__global__ void prep_trig_kernel() {
    int a = threadIdx.x;
    double th = (double)a * (2.0 * M_PI / (double)N_ANG);
    g_trig[a] = make_float2((float)cos(th), (float)sin(th));
}

// ---------------- kernel 0b: h = irfft(ramp)*(pi/N_ANG), fp64 DFT + tf32 split ----------------
__global__ __launch_bounds__(192) void prep_h_kernel(const float* __restrict__ ramp) {
    __shared__ double swarp[6];
    int n = blockIdx.x;
    int k = threadIdx.x;

    double term;
    if (k == 0) {
        double nyq = (double)ramp[DET_U/2] * (((n & 1) == 0) ? 1.0 : -1.0);
        term = (double)ramp[0] + nyq;
    } else {
        int m = (k * n) % DET_U;
        term = 2.0 * (double)ramp[k] * cos(2.0 * M_PI * (double)m / (double)DET_U);
    }
    #pragma unroll
    for (int off = 16; off > 0; off >>= 1)
        term += __shfl_down_sync(0xffffffffu, term, off);
    if ((k & 31) == 0) swarp[k >> 5] = term;
    __syncthreads();
    if (k == 0) {
        double acc = 0.0;
        #pragma unroll
        for (int w = 0; w < 6; w++) acc += swarp[w];
        float h  = (float)(acc / (double)DET_U * (M_PI / (double)N_ANG));
        float hi = tf32_rna(h);
        float lo = tf32_rna(h - hi);
        float2 p = make_float2(hi, lo);
        g_h2[n] = p;
        g_h2[n + DET_U] = p;
    }
}

// ---------------- kernel 1: filter as 3xTF32 tensor-core GEMM (circulant B) ----------------
#define SS2 388
#define FILT_SMEM ((64*SS2 + 768) * 8)

__global__ __launch_bounds__(512) void filt_gemm_kernel(const float* __restrict__ proj,
                                                        const float* __restrict__ redund) {
    extern __shared__ float2 sm2[];
    float2* S2  = sm2;
    float2* sh2 = sm2 + 64 * SS2;

    int tid  = threadIdx.x;
    int b    = blockIdx.x;
    int a    = b >> 2;
    int v0   = (b & 3) << 6;
    int row0 = b << 6;

    const float* prow = proj   + (size_t)row0 * DET_U;
    const float* rrow = redund + (size_t)a    * DET_U;

    for (int i = tid; i < 64 * DET_U; i += 512) {
        int r = i / DET_U;
        int c = i - r * DET_U;
        float vv = (float)(v0 + r) - CV;
        float uu = (float)c - CU;
        float cw = D_SD * rsqrtf(D_SD*D_SD + vv*vv + uu*uu);
        float val = prow[i] * cw * rrow[c];
        float hi = tf32_rna(val);
        float lo = tf32_rna(val - hi);
        S2[r * SS2 + c] = make_float2(hi, lo);
    }
    for (int i = tid; i < 2 * DET_U; i += 512) sh2[i] = g_h2[i];
    __syncthreads();

    int w    = tid >> 5;
    int lane = tid & 31;
    int gr   = lane >> 2;
    int tig  = lane & 3;
    int n0   = w * 24;

    float acc[4][3][4];
    #pragma unroll
    for (int mt = 0; mt < 4; mt++)
        #pragma unroll
        for (int nt = 0; nt < 3; nt++)
            #pragma unroll
            for (int q = 0; q < 4; q++) acc[mt][nt][q] = 0.f;

    const float2* Sb = S2 + gr * SS2 + tig;
    int bC = n0 + gr - tig + DET_U;

    #pragma unroll 4
    for (int ksg = 0; ksg < 48; ksg++) {
        int kg = ksg * 8;
        float2 A[4][4];
        #pragma unroll
        for (int mt = 0; mt < 4; mt++) {
            const float2* Ap = Sb + mt * (16 * SS2) + kg;
            A[mt][0] = Ap[0];
            A[mt][1] = Ap[8 * SS2];
            A[mt][2] = Ap[4];
            A[mt][3] = Ap[8 * SS2 + 4];
        }
        #pragma unroll
        for (int nt = 0; nt < 3; nt++) {
            int bi = bC + nt * 8 - kg;
            float2 b0 = sh2[bi];
            float2 b1 = sh2[bi - 4];
            #pragma unroll
            for (int mt = 0; mt < 4; mt++) {
                asm volatile(
                    "mma.sync.aligned.m16n8k8.row.col.f32.tf32.tf32.f32 "
                    "{%0,%1,%2,%3}, {%4,%5,%6,%7}, {%8,%9}, {%0,%1,%2,%3};"
                    : "+f"(acc[mt][nt][0]), "+f"(acc[mt][nt][1]),
                      "+f"(acc[mt][nt][2]), "+f"(acc[mt][nt][3])
                    : "r"(__float_as_uint(A[mt][0].x)), "r"(__float_as_uint(A[mt][1].x)),
                      "r"(__float_as_uint(A[mt][2].x)), "r"(__float_as_uint(A[mt][3].x)),
                      "r"(__float_as_uint(b0.x)), "r"(__float_as_uint(b1.x)));
                asm volatile(
                    "mma.sync.aligned.m16n8k8.row.col.f32.tf32.tf32.f32 "
                    "{%0,%1,%2,%3}, {%4,%5,%6,%7}, {%8,%9}, {%0,%1,%2,%3};"
                    : "+f"(acc[mt][nt][0]), "+f"(acc[mt][nt][1]),
                      "+f"(acc[mt][nt][2]), "+f"(acc[mt][nt][3])
                    : "r"(__float_as_uint(A[mt][0].x)), "r"(__float_as_uint(A[mt][1].x)),
                      "r"(__float_as_uint(A[mt][2].x)), "r"(__float_as_uint(A[mt][3].x)),
                      "r"(__float_as_uint(b0.y)), "r"(__float_as_uint(b1.y)));
                asm volatile(
                    "mma.sync.aligned.m16n8k8.row.col.f32.tf32.tf32.f32 "
                    "{%0,%1,%2,%3}, {%4,%5,%6,%7}, {%8,%9}, {%0,%1,%2,%3};"
                    : "+f"(acc[mt][nt][0]), "+f"(acc[mt][nt][1]),
                      "+f"(acc[mt][nt][2]), "+f"(acc[mt][nt][3])
                    : "r"(__float_as_uint(A[mt][0].y)), "r"(__float_as_uint(A[mt][1].y)),
                      "r"(__float_as_uint(A[mt][2].y)), "r"(__float_as_uint(A[mt][3].y)),
                      "r"(__float_as_uint(b0.x)), "r"(__float_as_uint(b1.x)));
            }
        }
    }

    __syncthreads();
    float* Sf = reinterpret_cast<float*>(sm2);
    #pragma unroll
    for (int mt = 0; mt < 4; mt++) {
        int r = 16 * mt + gr;
        #pragma unroll
        for (int nt = 0; nt < 3; nt++) {
            int col = n0 + nt * 8 + 2 * tig;
            *reinterpret_cast<float2*>(&Sf[r * 388 + col])       = make_float2(acc[mt][nt][0], acc[mt][nt][1]);
            *reinterpret_cast<float2*>(&Sf[(r + 8) * 388 + col]) = make_float2(acc[mt][nt][2], acc[mt][nt][3]);
        }
    }
    __syncthreads();

    for (int i = tid; i < 64 * 96; i += 512) {
        int r  = i / 96;
        int c4 = (i - r * 96) * 4;
        const float* Sp = &Sf[r * 388 + c4];
        float o0 = Sp[0], o1 = Sp[1], o2 = Sp[2], o3 = Sp[3];
        float o4 = (c4 == DET_U - 4) ? 0.0f : Sp[4];
        __half2 h0 = __floats2half2_rn(o0, o1);
        __half2 h1 = __floats2half2_rn(o1, o2);
        __half2 h2 = __floats2half2_rn(o2, o3);
        __half2 h3 = __floats2half2_rn(o3, o4);
        uint4 pack;
        pack.x = *reinterpret_cast<unsigned int*>(&h0);
        pack.y = *reinterpret_cast<unsigned int*>(&h1);
        pack.z = *reinterpret_cast<unsigned int*>(&h2);
        pack.w = *reinterpret_cast<unsigned int*>(&h3);
        *reinterpret_cast<uint4*>(g_filtH + (size_t)(row0 + r) * DET_U + c4) = pack;
    }
}

// ---------------- kernel 1b: build padded bilinear quads ----------------
__global__ __launch_bounds__(256) void requad_kernel() {
    int j  = threadIdx.x;
    if (j > 192) return;
    int vp = blockIdx.x;           // 0..256  (= v0+1)
    int a  = blockIdx.y;           // 0..255

    int c0 = 2 * j;
    uint4 outv = make_uint4(0u, 0u, 0u, 0u);

    bool rowok = (vp >= 1) && (vp <= 255);
    if (rowok && j >= 1) {
        int u0 = c0 - 2;
        const __half2* Hrow = g_filtH + (size_t)a * ROW_ELEMS + (size_t)(vp - 1) * DET_U + u0;
        uint2 top = *reinterpret_cast<const uint2*>(Hrow);
        uint2 bot = *reinterpret_cast<const uint2*>(Hrow + DET_U);

        __half2 A0 = *reinterpret_cast<__half2*>(&top.x);
        __half2 B0 = *reinterpret_cast<__half2*>(&bot.x);
        __half2 lo0 = __lows2half2(A0, B0);
        __half2 hi0 = __highs2half2(A0, B0);
        outv.x = *reinterpret_cast<unsigned int*>(&lo0);
        outv.y = *reinterpret_cast<unsigned int*>(&hi0);

        if (j <= 191) {
            __half2 A1 = *reinterpret_cast<__half2*>(&top.y);
            __half2 B1 = *reinterpret_cast<__half2*>(&bot.y);
            __half2 lo1 = __lows2half2(A1, B1);
            __half2 hi1 = __highs2half2(A1, B1);
            outv.z = *reinterpret_cast<unsigned int*>(&lo1);
            outv.w = *reinterpret_cast<unsigned int*>(&hi1);
        }
    }

    size_t qidx = ((size_t)a * QS_ANG + (size_t)vp * QS_U + c0) >> 1;
    g_filtQ4[qidx] = outv;
}

// ---------------- kernel 2: backprojection, angle-split partials ----------------
#define ZPT 8
__global__ __launch_bounds__(128) void bp_kernel() {
    __shared__ float2 strig[ACHUNK];
    int tid = threadIdx.x;
    int ach = blockIdx.z;
    int a0  = ach * ACHUNK;
    for (int i = tid; i < ACHUNK; i += 128) strig[i] = g_trig[a0 + i];
    __syncthreads();

    int x  = tid;
    int y  = blockIdx.x;
    int z0 = blockIdx.y * ZPT;

    float xc  = (float)x  - CC;
    float yc  = (float)y  - CC;
    float zc0 = (float)z0 - CC;

    float acc[ZPT];
    #pragma unroll
    for (int j = 0; j < ZPT; j++) acc[j] = 0.f;

    const uint2* Q = reinterpret_cast<const uint2*>(g_filtQ4) + (size_t)a0 * QS_ANG;

    #pragma unroll 2
    for (int ai = 0; ai < ACHUNK; ai++) {
        float2 cs = strig[ai];
        float c = cs.x, s = cs.y;
        float t = yc * c - xc * s;
        float r = D_SO - (xc * c + yc * s);
        float rinv = __fdividef(1.0f, r);

        float iu  = fmaf(D_SD * t, rinv, CU);
        int   u0r = __float2int_rd(iu);
        float fu  = iu - __int2float_rn(u0r);
        int   u0i = min(max(u0r, -1), DET_U - 1);
        __half2 fu2 = __float2half2_rn(fu);

        float wq = D_SO * rinv;
        float w  = wq * wq;

        float kz  = D_SD * rinv;
        float iv0 = fmaf(kz, zc0, CV);

        const uint2* rowp = Q + (size_t)ai * QS_ANG + (QS_U + 2) + u0i;

        #pragma unroll
        for (int j = 0; j < ZPT; j++) {
            float iv  = fmaf(kz, (float)j, iv0);
            int   v0r = __float2int_rd(iv);
            float fv  = iv - __int2float_rn(v0r);
            int   v0i = min(max(v0r, -1), DET_V - 1);
            uint2 q = rowp[(size_t)v0i * QS_U];
            __half2 A = *reinterpret_cast<__half2*>(&q.x);
            __half2 B = *reinterpret_cast<__half2*>(&q.y);
            __half2 E = __hfma2(fu2, __hsub2(B, A), A);
            float2 e = __half22float2(E);
            float val = fmaf(fv, e.y - e.x, e.x);
            acc[j] = fmaf(val, w, acc[j]);
        }
    }

    float* part = g_part + (size_t)ach * VOL_ELEMS;
    size_t obase = ((size_t)z0 * VOL_N + y) * VOL_N + x;
    #pragma unroll
    for (int j = 0; j < ZPT; j++) {
        part[obase + (size_t)j * VOL_N * VOL_N] = acc[j];
    }
}

// ---------------- kernel 3: sum partials ----------------
__global__ __launch_bounds__(256) void add_kernel(float* __restrict__ out) {
    size_t i = ((size_t)blockIdx.x * 256 + threadIdx.x) * 4;
    float4 p0 = *reinterpret_cast<const float4*>(g_part + i);
    float4 p1 = *reinterpret_cast<const float4*>(g_part + VOL_ELEMS + i);
    float4 p2 = *reinterpret_cast<const float4*>(g_part + 2*(size_t)VOL_ELEMS + i);
    float4 p3 = *reinterpret_cast<const float4*>(g_part + 3*(size_t)VOL_ELEMS + i);
    float4 o;
    o.x = (p0.x + p1.x) + (p2.x + p3.x);
    o.y = (p0.y + p1.y) + (p2.y + p3.y);
    o.z = (p0.z + p1.z) + (p2.z + p3.z);
    o.w = (p0.w + p1.w) + (p2.w + p3.w);
    *reinterpret_cast<float4*>(out + i) = o;
}

// ---------------- launch ----------------
extern "C" void kernel_launch(void* const* d_in, const int* in_sizes, int n_in,
                              void* d_out, int out_size) {
    const float* proj   = nullptr;
    const float* ramp   = nullptr;
    const float* redund = nullptr;
    for (int i = 0; i < n_in; i++) {
        if (in_sizes[i] == DET_U/2 + 1)                    ramp   = (const float*)d_in[i];
        else if (in_sizes[i] == N_ANG * DET_U)             redund = (const float*)d_in[i];
        else if (in_sizes[i] == N_ANG * DET_V * DET_U)     proj   = (const float*)d_in[i];
    }

    cudaFuncSetAttribute(filt_gemm_kernel,
                         cudaFuncAttributeMaxDynamicSharedMemorySize, FILT_SMEM);

    prep_trig_kernel<<<1, N_ANG>>>();
    prep_h_kernel<<<DET_U, 192>>>(ramp);
    filt_gemm_kernel<<<(N_ANG*DET_V)/64, 512, FILT_SMEM>>>(proj, redund);
    dim3 qgrid(QS_ROWS, N_ANG);
    requad_kernel<<<qgrid, 256>>>();
    dim3 grid(VOL_N, VOL_N / ZPT, ASPLIT);
    bp_kernel<<<grid, 128>>>();
    add_kernel<<<VOL_ELEMS/(256*4), 256>>>((float*)d_out);
}

// round 8
// speedup vs baseline: 1.5157x; 1.1312x over previous
#include <cuda_runtime.h>
#include <cuda_fp16.h>
#include <math.h>
#include <stdint.h>

// ---------------- problem constants ----------------
#define N_ANG   256
#define DET_V   256
#define DET_U   384
#define VOL_N   128
#define D_SO    500.0f
#define D_SD    1000.0f
#define CU      191.5f
#define CV      127.5f
#define CC      63.5f
#define ROW_ELEMS (DET_V*DET_U)
#define VOL_ELEMS (VOL_N*VOL_N*VOL_N)

// quad buffer geometry (row index = v0 + 30; rows 0..28 and 286..313 are zero pad)
#define QS_U    392                 // uint2 quads per row (cols 0..391; used 0..385)
#define QS_ROWS 314                 // covers v0r in [-30, 283] unclamped
#define QS_ANG  (QS_U*QS_ROWS)      // quads per angle
#define QROW_SHIFT 29               // requad writes at row = vp_old + 29 (vp_old = v0+1)

// angle split for BP occupancy
#define ASPLIT  8
#define ACHUNK  (N_ANG/ASPLIT)      // 32

// ---------------- device scratch ----------------
__device__ float2  g_h2[2*DET_U];                        // (hi,lo) tf32 split of ramp kernel
__device__ float2  g_trig[N_ANG];                        // (cos, sin) per angle
__device__ __half2 g_filtH[(size_t)N_ANG*DET_V*DET_U];   // filtered proj, (p[u],p[u+1]) pairs
__device__ uint4   g_filtQ4[(size_t)N_ANG*QS_ANG/2];     // padded bilinear quads (252MB)
__device__ float   g_part[(size_t)ASPLIT*VOL_ELEMS];     // partial volumes (67MB)

__device__ __forceinline__ float tf32_rna(float x) {
    uint32_t t;
    asm("cvt.rna.tf32.f32 %0, %1;" : "=r"(t) : "f"(x));
    return __uint_as_float(t);
}

// ---------------- kernel 0a: trig table ----------------
__global__ void prep_trig_kernel() {
    int a = threadIdx.x;
    double th = (double)a * (2.0 * M_PI / (double)N_ANG);
    g_trig[a] = make_float2((float)cos(th), (float)sin(th));
}

// ---------------- kernel 0b: h = irfft(ramp)*(pi/N_ANG), fp64 DFT + tf32 split ----------------
__global__ __launch_bounds__(192) void prep_h_kernel(const float* __restrict__ ramp) {
    __shared__ double swarp[6];
    int n = blockIdx.x;
    int k = threadIdx.x;

    double term;
    if (k == 0) {
        double nyq = (double)ramp[DET_U/2] * (((n & 1) == 0) ? 1.0 : -1.0);
        term = (double)ramp[0] + nyq;
    } else {
        int m = (k * n) % DET_U;
        term = 2.0 * (double)ramp[k] * cos(2.0 * M_PI * (double)m / (double)DET_U);
    }
    #pragma unroll
    for (int off = 16; off > 0; off >>= 1)
        term += __shfl_down_sync(0xffffffffu, term, off);
    if ((k & 31) == 0) swarp[k >> 5] = term;
    __syncthreads();
    if (k == 0) {
        double acc = 0.0;
        #pragma unroll
        for (int w = 0; w < 6; w++) acc += swarp[w];
        float h  = (float)(acc / (double)DET_U * (M_PI / (double)N_ANG));
        float hi = tf32_rna(h);
        float lo = tf32_rna(h - hi);
        float2 p = make_float2(hi, lo);
        g_h2[n] = p;
        g_h2[n + DET_U] = p;
    }
}

// ---------------- kernel 1: filter as 3xTF32 tensor-core GEMM (circulant B) ----------------
#define SS2 388
#define FILT_SMEM ((64*SS2 + 768) * 8)

__global__ __launch_bounds__(512) void filt_gemm_kernel(const float* __restrict__ proj,
                                                        const float* __restrict__ redund) {
    extern __shared__ float2 sm2[];
    float2* S2  = sm2;
    float2* sh2 = sm2 + 64 * SS2;

    int tid  = threadIdx.x;
    int b    = blockIdx.x;
    int a    = b >> 2;
    int v0   = (b & 3) << 6;
    int row0 = b << 6;

    const float* prow = proj   + (size_t)row0 * DET_U;
    const float* rrow = redund + (size_t)a    * DET_U;

    for (int i = tid; i < 64 * DET_U; i += 512) {
        int r = i / DET_U;
        int c = i - r * DET_U;
        float vv = (float)(v0 + r) - CV;
        float uu = (float)c - CU;
        float cw = D_SD * rsqrtf(D_SD*D_SD + vv*vv + uu*uu);
        float val = prow[i] * cw * rrow[c];
        float hi = tf32_rna(val);
        float lo = tf32_rna(val - hi);
        S2[r * SS2 + c] = make_float2(hi, lo);
    }
    for (int i = tid; i < 2 * DET_U; i += 512) sh2[i] = g_h2[i];
    __syncthreads();

    int w    = tid >> 5;
    int lane = tid & 31;
    int gr   = lane >> 2;
    int tig  = lane & 3;
    int n0   = w * 24;

    float acc[4][3][4];
    #pragma unroll
    for (int mt = 0; mt < 4; mt++)
        #pragma unroll
        for (int nt = 0; nt < 3; nt++)
            #pragma unroll
            for (int q = 0; q < 4; q++) acc[mt][nt][q] = 0.f;

    const float2* Sb = S2 + gr * SS2 + tig;
    int bC = n0 + gr - tig + DET_U;

    #pragma unroll 4
    for (int ksg = 0; ksg < 48; ksg++) {
        int kg = ksg * 8;
        float2 A[4][4];
        #pragma unroll
        for (int mt = 0; mt < 4; mt++) {
            const float2* Ap = Sb + mt * (16 * SS2) + kg;
            A[mt][0] = Ap[0];
            A[mt][1] = Ap[8 * SS2];
            A[mt][2] = Ap[4];
            A[mt][3] = Ap[8 * SS2 + 4];
        }
        #pragma unroll
        for (int nt = 0; nt < 3; nt++) {
            int bi = bC + nt * 8 - kg;
            float2 b0 = sh2[bi];
            float2 b1 = sh2[bi - 4];
            #pragma unroll
            for (int mt = 0; mt < 4; mt++) {
                asm volatile(
                    "mma.sync.aligned.m16n8k8.row.col.f32.tf32.tf32.f32 "
                    "{%0,%1,%2,%3}, {%4,%5,%6,%7}, {%8,%9}, {%0,%1,%2,%3};"
                    : "+f"(acc[mt][nt][0]), "+f"(acc[mt][nt][1]),
                      "+f"(acc[mt][nt][2]), "+f"(acc[mt][nt][3])
                    : "r"(__float_as_uint(A[mt][0].x)), "r"(__float_as_uint(A[mt][1].x)),
                      "r"(__float_as_uint(A[mt][2].x)), "r"(__float_as_uint(A[mt][3].x)),
                      "r"(__float_as_uint(b0.x)), "r"(__float_as_uint(b1.x)));
                asm volatile(
                    "mma.sync.aligned.m16n8k8.row.col.f32.tf32.tf32.f32 "
                    "{%0,%1,%2,%3}, {%4,%5,%6,%7}, {%8,%9}, {%0,%1,%2,%3};"
                    : "+f"(acc[mt][nt][0]), "+f"(acc[mt][nt][1]),
                      "+f"(acc[mt][nt][2]), "+f"(acc[mt][nt][3])
                    : "r"(__float_as_uint(A[mt][0].x)), "r"(__float_as_uint(A[mt][1].x)),
                      "r"(__float_as_uint(A[mt][2].x)), "r"(__float_as_uint(A[mt][3].x)),
                      "r"(__float_as_uint(b0.y)), "r"(__float_as_uint(b1.y)));
                asm volatile(
                    "mma.sync.aligned.m16n8k8.row.col.f32.tf32.tf32.f32 "
                    "{%0,%1,%2,%3}, {%4,%5,%6,%7}, {%8,%9}, {%0,%1,%2,%3};"
                    : "+f"(acc[mt][nt][0]), "+f"(acc[mt][nt][1]),
                      "+f"(acc[mt][nt][2]), "+f"(acc[mt][nt][3])
                    : "r"(__float_as_uint(A[mt][0].y)), "r"(__float_as_uint(A[mt][1].y)),
                      "r"(__float_as_uint(A[mt][2].y)), "r"(__float_as_uint(A[mt][3].y)),
                      "r"(__float_as_uint(b0.x)), "r"(__float_as_uint(b1.x)));
            }
        }
    }

    __syncthreads();
    float* Sf = reinterpret_cast<float*>(sm2);
    #pragma unroll
    for (int mt = 0; mt < 4; mt++) {
        int r = 16 * mt + gr;
        #pragma unroll
        for (int nt = 0; nt < 3; nt++) {
            int col = n0 + nt * 8 + 2 * tig;
            *reinterpret_cast<float2*>(&Sf[r * 388 + col])       = make_float2(acc[mt][nt][0], acc[mt][nt][1]);
            *reinterpret_cast<float2*>(&Sf[(r + 8) * 388 + col]) = make_float2(acc[mt][nt][2], acc[mt][nt][3]);
        }
    }
    __syncthreads();

    for (int i = tid; i < 64 * 96; i += 512) {
        int r  = i / 96;
        int c4 = (i - r * 96) * 4;
        const float* Sp = &Sf[r * 388 + c4];
        float o0 = Sp[0], o1 = Sp[1], o2 = Sp[2], o3 = Sp[3];
        float o4 = (c4 == DET_U - 4) ? 0.0f : Sp[4];
        __half2 h0 = __floats2half2_rn(o0, o1);
        __half2 h1 = __floats2half2_rn(o1, o2);
        __half2 h2 = __floats2half2_rn(o2, o3);
        __half2 h3 = __floats2half2_rn(o3, o4);
        uint4 pack;
        pack.x = *reinterpret_cast<unsigned int*>(&h0);
        pack.y = *reinterpret_cast<unsigned int*>(&h1);
        pack.z = *reinterpret_cast<unsigned int*>(&h2);
        pack.w = *reinterpret_cast<unsigned int*>(&h3);
        *reinterpret_cast<uint4*>(g_filtH + (size_t)(row0 + r) * DET_U + c4) = pack;
    }
}

// ---------------- kernel 1a: zero the padded border rows of the quad buffer ----------------
// rows [0,29) and [286,314) of every angle slab
__global__ __launch_bounds__(196) void zero_border_kernel() {
    int t  = threadIdx.x;          // 0..195, each writes one uint4 (2 quads)
    int rz = blockIdx.x;           // 0..56
    int a  = blockIdx.y;
    int row = (rz < 29) ? rz : (rz + 257);   // 0..28 or 286..313
    size_t q4 = (((size_t)a * QS_ANG + (size_t)row * QS_U) >> 1) + t;
    g_filtQ4[q4] = make_uint4(0u, 0u, 0u, 0u);
}

// ---------------- kernel 1b: build padded bilinear quads ----------------
// Q[a][v0+30][u0+2] = (p00,p10 | p01,p11); writes rows 29..285
__global__ __launch_bounds__(256) void requad_kernel() {
    int j  = threadIdx.x;
    if (j > 192) return;
    int vp = blockIdx.x;           // 0..256  (= v0+1)
    int a  = blockIdx.y;

    int c0 = 2 * j;
    uint4 outv = make_uint4(0u, 0u, 0u, 0u);

    bool rowok = (vp >= 1) && (vp <= 255);
    if (rowok && j >= 1) {
        int u0 = c0 - 2;
        const __half2* Hrow = g_filtH + (size_t)a * ROW_ELEMS + (size_t)(vp - 1) * DET_U + u0;
        uint2 top = *reinterpret_cast<const uint2*>(Hrow);
        uint2 bot = *reinterpret_cast<const uint2*>(Hrow + DET_U);

        __half2 A0 = *reinterpret_cast<__half2*>(&top.x);
        __half2 B0 = *reinterpret_cast<__half2*>(&bot.x);
        __half2 lo0 = __lows2half2(A0, B0);
        __half2 hi0 = __highs2half2(A0, B0);
        outv.x = *reinterpret_cast<unsigned int*>(&lo0);
        outv.y = *reinterpret_cast<unsigned int*>(&hi0);

        if (j <= 191) {
            __half2 A1 = *reinterpret_cast<__half2*>(&top.y);
            __half2 B1 = *reinterpret_cast<__half2*>(&bot.y);
            __half2 lo1 = __lows2half2(A1, B1);
            __half2 hi1 = __highs2half2(A1, B1);
            outv.z = *reinterpret_cast<unsigned int*>(&lo1);
            outv.w = *reinterpret_cast<unsigned int*>(&hi1);
        }
    }

    size_t qidx = ((size_t)a * QS_ANG + (size_t)(vp + QROW_SHIFT) * QS_U + c0) >> 1;
    g_filtQ4[qidx] = outv;
}

// ---------------- kernel 2: backprojection, angle-split partials, no v-clamp ----------------
#define ZPT 8
__global__ __launch_bounds__(128, 12) void bp_kernel() {
    __shared__ float2 strig[ACHUNK];
    int tid = threadIdx.x;
    int ach = blockIdx.z;
    int a0  = ach * ACHUNK;
    for (int i = tid; i < ACHUNK; i += 128) strig[i] = g_trig[a0 + i];
    __syncthreads();

    int x  = tid;
    int y  = blockIdx.x;
    int z0 = blockIdx.y * ZPT;

    float xc  = (float)x  - CC;
    float yc  = (float)y  - CC;
    float zc0 = (float)z0 - CC;

    float acc[ZPT];
    #pragma unroll
    for (int j = 0; j < ZPT; j++) acc[j] = 0.f;

    const uint2* Q = reinterpret_cast<const uint2*>(g_filtQ4) + (size_t)a0 * QS_ANG;

    #pragma unroll 2
    for (int ai = 0; ai < ACHUNK; ai++) {
        float2 cs = strig[ai];
        float c = cs.x, s = cs.y;
        float t = yc * c - xc * s;
        float r = D_SO - (xc * c + yc * s);
        float rinv = __fdividef(1.0f, r);

        float iu  = fmaf(D_SD * t, rinv, CU);
        int   u0r = __float2int_rd(iu);
        float fu  = iu - __int2float_rn(u0r);
        int   u0i = min(max(u0r, -1), DET_U - 1);
        __half2 fu2 = __float2half2_rn(fu);

        float wq = D_SO * rinv;
        float w  = wq * wq;

        float kz  = D_SD * rinv;
        float iv0 = fmaf(kz, zc0, CV);

        // row index = v0r + 30 (padded, always in range); col = u0i + 2
        const uint2* rowp = Q + (size_t)ai * QS_ANG + (30 * QS_U + 2) + u0i;

        #pragma unroll
        for (int j = 0; j < ZPT; j++) {
            float iv  = fmaf(kz, (float)j, iv0);
            int   v0r = __float2int_rd(iv);
            float fv  = iv - __int2float_rn(v0r);
            uint2 q = rowp[(long)v0r * QS_U];
            __half2 A = *reinterpret_cast<__half2*>(&q.x);
            __half2 B = *reinterpret_cast<__half2*>(&q.y);
            __half2 E = __hfma2(fu2, __hsub2(B, A), A);
            float2 e = __half22float2(E);
            float val = fmaf(fv, e.y - e.x, e.x);
            acc[j] = fmaf(val, w, acc[j]);
        }
    }

    float* part = g_part + (size_t)ach * VOL_ELEMS;
    size_t obase = ((size_t)z0 * VOL_N + y) * VOL_N + x;
    #pragma unroll
    for (int j = 0; j < ZPT; j++) {
        part[obase + (size_t)j * VOL_N * VOL_N] = acc[j];
    }
}

// ---------------- kernel 3: sum partials ----------------
__global__ __launch_bounds__(256) void add_kernel(float* __restrict__ out) {
    size_t i = ((size_t)blockIdx.x * 256 + threadIdx.x) * 4;
    float4 o = make_float4(0.f, 0.f, 0.f, 0.f);
    #pragma unroll
    for (int p = 0; p < ASPLIT; p++) {
        float4 v = *reinterpret_cast<const float4*>(g_part + (size_t)p * VOL_ELEMS + i);
        o.x += v.x; o.y += v.y; o.z += v.z; o.w += v.w;
    }
    *reinterpret_cast<float4*>(out + i) = o;
}

// ---------------- launch ----------------
extern "C" void kernel_launch(void* const* d_in, const int* in_sizes, int n_in,
                              void* d_out, int out_size) {
    const float* proj   = nullptr;
    const float* ramp   = nullptr;
    const float* redund = nullptr;
    for (int i = 0; i < n_in; i++) {
        if (in_sizes[i] == DET_U/2 + 1)                    ramp   = (const float*)d_in[i];
        else if (in_sizes[i] == N_ANG * DET_U)             redund = (const float*)d_in[i];
        else if (in_sizes[i] == N_ANG * DET_V * DET_U)     proj   = (const float*)d_in[i];
    }

    cudaFuncSetAttribute(filt_gemm_kernel,
                         cudaFuncAttributeMaxDynamicSharedMemorySize, FILT_SMEM);

    prep_trig_kernel<<<1, N_ANG>>>();
    prep_h_kernel<<<DET_U, 192>>>(ramp);
    filt_gemm_kernel<<<(N_ANG*DET_V)/64, 512, FILT_SMEM>>>(proj, redund);
    dim3 zgrid(57, N_ANG);
    zero_border_kernel<<<zgrid, 196>>>();
    dim3 qgrid(257, N_ANG);
    requad_kernel<<<qgrid, 256>>>();
    dim3 grid(VOL_N, VOL_N / ZPT, ASPLIT);
    bp_kernel<<<grid, 128>>>();
    add_kernel<<<VOL_ELEMS/(256*4), 256>>>((float*)d_out);
}

// round 9
// speedup vs baseline: 1.5928x; 1.0509x over previous
#include <cuda_runtime.h>
#include <cuda_fp16.h>
#include <math.h>
#include <stdint.h>

// ---------------- problem constants ----------------
#define N_ANG   256
#define DET_V   256
#define DET_U   384
#define VOL_N   128
#define D_SO    500.0f
#define D_SD    1000.0f
#define CU      191.5f
#define CV      127.5f
#define CC      63.5f
#define ROW_ELEMS (DET_V*DET_U)
#define VOL_ELEMS (VOL_N*VOL_N*VOL_N)

// quad buffer geometry (row index = v0 + 30; rows 0..28 and 286..313 stay zero)
#define QS_U    392
#define QS_ROWS 314
#define QS_ANG  (QS_U*QS_ROWS)
#define QROW_SHIFT 29

// angle split for BP occupancy
#define ASPLIT  8
#define ACHUNK  (N_ANG/ASPLIT)      // 32

// ---------------- device scratch (zero-initialized at module load) ----------------
__device__ float2  g_h2[2*DET_U];
__device__ float2  g_trig[N_ANG];
__device__ __half2 g_filtH[(size_t)N_ANG*DET_V*DET_U];
__device__ uint4   g_filtQ4[(size_t)N_ANG*QS_ANG/2];     // borders rely on zero-init (never written)
__device__ float   g_part[(size_t)ASPLIT*VOL_ELEMS];

__device__ __forceinline__ float tf32_rna(float x) {
    uint32_t t;
    asm("cvt.rna.tf32.f32 %0, %1;" : "=r"(t) : "f"(x));
    return __uint_as_float(t);
}

// ---------------- kernel 0a: zero border rows (idempotent; borders already zero) ----------------
// kept as launch #1 so filt_gemm lands at slot 4 for the ncu capture
__global__ __launch_bounds__(196) void zero_border_kernel() {
    int t  = threadIdx.x;
    int rz = blockIdx.x;
    int a  = blockIdx.y;
    int row = (rz < 29) ? rz : (rz + 257);
    size_t q4 = (((size_t)a * QS_ANG + (size_t)row * QS_U) >> 1) + t;
    g_filtQ4[q4] = make_uint4(0u, 0u, 0u, 0u);
}

// ---------------- kernel 0b: trig table ----------------
__global__ void prep_trig_kernel() {
    int a = threadIdx.x;
    double th = (double)a * (2.0 * M_PI / (double)N_ANG);
    g_trig[a] = make_float2((float)cos(th), (float)sin(th));
}

// ---------------- kernel 0c: h = irfft(ramp)*(pi/N_ANG), fp64 DFT + tf32 split ----------------
__global__ __launch_bounds__(192) void prep_h_kernel(const float* __restrict__ ramp) {
    __shared__ double swarp[6];
    int n = blockIdx.x;
    int k = threadIdx.x;

    double term;
    if (k == 0) {
        double nyq = (double)ramp[DET_U/2] * (((n & 1) == 0) ? 1.0 : -1.0);
        term = (double)ramp[0] + nyq;
    } else {
        int m = (k * n) % DET_U;
        term = 2.0 * (double)ramp[k] * cos(2.0 * M_PI * (double)m / (double)DET_U);
    }
    #pragma unroll
    for (int off = 16; off > 0; off >>= 1)
        term += __shfl_down_sync(0xffffffffu, term, off);
    if ((k & 31) == 0) swarp[k >> 5] = term;
    __syncthreads();
    if (k == 0) {
        double acc = 0.0;
        #pragma unroll
        for (int w = 0; w < 6; w++) acc += swarp[w];
        float h  = (float)(acc / (double)DET_U * (M_PI / (double)N_ANG));
        float hi = tf32_rna(h);
        float lo = tf32_rna(h - hi);
        float2 p = make_float2(hi, lo);
        g_h2[n] = p;
        g_h2[n + DET_U] = p;
    }
}

// ---------------- kernel 1: filter as 3xTF32 tensor-core GEMM (circulant B) ----------------
#define SS2 388
#define FILT_SMEM ((64*SS2 + 768) * 8)

__global__ __launch_bounds__(512) void filt_gemm_kernel(const float* __restrict__ proj,
                                                        const float* __restrict__ redund) {
    extern __shared__ float2 sm2[];
    float2* S2  = sm2;
    float2* sh2 = sm2 + 64 * SS2;

    int tid  = threadIdx.x;
    int b    = blockIdx.x;
    int a    = b >> 2;
    int v0   = (b & 3) << 6;
    int row0 = b << 6;

    const float* prow = proj   + (size_t)row0 * DET_U;
    const float* rrow = redund + (size_t)a    * DET_U;

    for (int i = tid; i < 64 * DET_U; i += 512) {
        int r = i / DET_U;
        int c = i - r * DET_U;
        float vv = (float)(v0 + r) - CV;
        float uu = (float)c - CU;
        float cw = D_SD * rsqrtf(D_SD*D_SD + vv*vv + uu*uu);
        float val = prow[i] * cw * rrow[c];
        float hi = tf32_rna(val);
        float lo = tf32_rna(val - hi);
        S2[r * SS2 + c] = make_float2(hi, lo);
    }
    for (int i = tid; i < 2 * DET_U; i += 512) sh2[i] = g_h2[i];
    __syncthreads();

    int w    = tid >> 5;
    int lane = tid & 31;
    int gr   = lane >> 2;
    int tig  = lane & 3;
    int n0   = w * 24;

    float acc[4][3][4];
    #pragma unroll
    for (int mt = 0; mt < 4; mt++)
        #pragma unroll
        for (int nt = 0; nt < 3; nt++)
            #pragma unroll
            for (int q = 0; q < 4; q++) acc[mt][nt][q] = 0.f;

    const float2* Sb = S2 + gr * SS2 + tig;
    int bC = n0 + gr - tig + DET_U;

    #pragma unroll 4
    for (int ksg = 0; ksg < 48; ksg++) {
        int kg = ksg * 8;
        float2 A[4][4];
        #pragma unroll
        for (int mt = 0; mt < 4; mt++) {
            const float2* Ap = Sb + mt * (16 * SS2) + kg;
            A[mt][0] = Ap[0];
            A[mt][1] = Ap[8 * SS2];
            A[mt][2] = Ap[4];
            A[mt][3] = Ap[8 * SS2 + 4];
        }
        #pragma unroll
        for (int nt = 0; nt < 3; nt++) {
            int bi = bC + nt * 8 - kg;
            float2 b0 = sh2[bi];
            float2 b1 = sh2[bi - 4];
            #pragma unroll
            for (int mt = 0; mt < 4; mt++) {
                asm volatile(
                    "mma.sync.aligned.m16n8k8.row.col.f32.tf32.tf32.f32 "
                    "{%0,%1,%2,%3}, {%4,%5,%6,%7}, {%8,%9}, {%0,%1,%2,%3};"
                    : "+f"(acc[mt][nt][0]), "+f"(acc[mt][nt][1]),
                      "+f"(acc[mt][nt][2]), "+f"(acc[mt][nt][3])
                    : "r"(__float_as_uint(A[mt][0].x)), "r"(__float_as_uint(A[mt][1].x)),
                      "r"(__float_as_uint(A[mt][2].x)), "r"(__float_as_uint(A[mt][3].x)),
                      "r"(__float_as_uint(b0.x)), "r"(__float_as_uint(b1.x)));
                asm volatile(
                    "mma.sync.aligned.m16n8k8.row.col.f32.tf32.tf32.f32 "
                    "{%0,%1,%2,%3}, {%4,%5,%6,%7}, {%8,%9}, {%0,%1,%2,%3};"
                    : "+f"(acc[mt][nt][0]), "+f"(acc[mt][nt][1]),
                      "+f"(acc[mt][nt][2]), "+f"(acc[mt][nt][3])
                    : "r"(__float_as_uint(A[mt][0].x)), "r"(__float_as_uint(A[mt][1].x)),
                      "r"(__float_as_uint(A[mt][2].x)), "r"(__float_as_uint(A[mt][3].x)),
                      "r"(__float_as_uint(b0.y)), "r"(__float_as_uint(b1.y)));
                asm volatile(
                    "mma.sync.aligned.m16n8k8.row.col.f32.tf32.tf32.f32 "
                    "{%0,%1,%2,%3}, {%4,%5,%6,%7}, {%8,%9}, {%0,%1,%2,%3};"
                    : "+f"(acc[mt][nt][0]), "+f"(acc[mt][nt][1]),
                      "+f"(acc[mt][nt][2]), "+f"(acc[mt][nt][3])
                    : "r"(__float_as_uint(A[mt][0].y)), "r"(__float_as_uint(A[mt][1].y)),
                      "r"(__float_as_uint(A[mt][2].y)), "r"(__float_as_uint(A[mt][3].y)),
                      "r"(__float_as_uint(b0.x)), "r"(__float_as_uint(b1.x)));
            }
        }
    }

    __syncthreads();
    float* Sf = reinterpret_cast<float*>(sm2);
    #pragma unroll
    for (int mt = 0; mt < 4; mt++) {
        int r = 16 * mt + gr;
        #pragma unroll
        for (int nt = 0; nt < 3; nt++) {
            int col = n0 + nt * 8 + 2 * tig;
            *reinterpret_cast<float2*>(&Sf[r * 388 + col])       = make_float2(acc[mt][nt][0], acc[mt][nt][1]);
            *reinterpret_cast<float2*>(&Sf[(r + 8) * 388 + col]) = make_float2(acc[mt][nt][2], acc[mt][nt][3]);
        }
    }
    __syncthreads();

    for (int i = tid; i < 64 * 96; i += 512) {
        int r  = i / 96;
        int c4 = (i - r * 96) * 4;
        const float* Sp = &Sf[r * 388 + c4];
        float o0 = Sp[0], o1 = Sp[1], o2 = Sp[2], o3 = Sp[3];
        float o4 = (c4 == DET_U - 4) ? 0.0f : Sp[4];
        __half2 h0 = __floats2half2_rn(o0, o1);
        __half2 h1 = __floats2half2_rn(o1, o2);
        __half2 h2 = __floats2half2_rn(o2, o3);
        __half2 h3 = __floats2half2_rn(o3, o4);
        uint4 pack;
        pack.x = *reinterpret_cast<unsigned int*>(&h0);
        pack.y = *reinterpret_cast<unsigned int*>(&h1);
        pack.z = *reinterpret_cast<unsigned int*>(&h2);
        pack.w = *reinterpret_cast<unsigned int*>(&h3);
        *reinterpret_cast<uint4*>(g_filtH + (size_t)(row0 + r) * DET_U + c4) = pack;
    }
}

// ---------------- kernel 1b: build padded bilinear quads (rows 29..285) ----------------
__global__ __launch_bounds__(256) void requad_kernel() {
    int j  = threadIdx.x;
    if (j > 192) return;
    int vp = blockIdx.x;           // 0..256  (= v0+1)
    int a  = blockIdx.y;

    int c0 = 2 * j;
    uint4 outv = make_uint4(0u, 0u, 0u, 0u);

    bool rowok = (vp >= 1) && (vp <= 255);
    if (rowok && j >= 1) {
        int u0 = c0 - 2;
        const __half2* Hrow = g_filtH + (size_t)a * ROW_ELEMS + (size_t)(vp - 1) * DET_U + u0;
        uint2 top = *reinterpret_cast<const uint2*>(Hrow);
        uint2 bot = *reinterpret_cast<const uint2*>(Hrow + DET_U);

        __half2 A0 = *reinterpret_cast<__half2*>(&top.x);
        __half2 B0 = *reinterpret_cast<__half2*>(&bot.x);
        __half2 lo0 = __lows2half2(A0, B0);
        __half2 hi0 = __highs2half2(A0, B0);
        outv.x = *reinterpret_cast<unsigned int*>(&lo0);
        outv.y = *reinterpret_cast<unsigned int*>(&hi0);

        if (j <= 191) {
            __half2 A1 = *reinterpret_cast<__half2*>(&top.y);
            __half2 B1 = *reinterpret_cast<__half2*>(&bot.y);
            __half2 lo1 = __lows2half2(A1, B1);
            __half2 hi1 = __highs2half2(A1, B1);
            outv.z = *reinterpret_cast<unsigned int*>(&lo1);
            outv.w = *reinterpret_cast<unsigned int*>(&hi1);
        }
    }

    size_t qidx = ((size_t)a * QS_ANG + (size_t)(vp + QROW_SHIFT) * QS_U + c0) >> 1;
    g_filtQ4[qidx] = outv;
}

// ---------------- kernel 2: backprojection, two-phase batched loads ----------------
#define ZPT 8
__global__ __launch_bounds__(128, 10) void bp_kernel() {
    __shared__ float2 strig[ACHUNK];
    int tid = threadIdx.x;
    int ach = blockIdx.z;
    int a0  = ach * ACHUNK;
    for (int i = tid; i < ACHUNK; i += 128) strig[i] = g_trig[a0 + i];
    __syncthreads();

    int x  = tid;
    int y  = blockIdx.x;
    int z0 = blockIdx.y * ZPT;

    float xc  = (float)x  - CC;
    float yc  = (float)y  - CC;
    float zc0 = (float)z0 - CC;

    float acc[ZPT];
    #pragma unroll
    for (int j = 0; j < ZPT; j++) acc[j] = 0.f;

    const uint2* Q = reinterpret_cast<const uint2*>(g_filtQ4) + (size_t)a0 * QS_ANG;

    #pragma unroll 2
    for (int ai = 0; ai < ACHUNK; ai++) {
        float2 cs = strig[ai];
        float c = cs.x, s = cs.y;
        float t = yc * c - xc * s;
        float r = D_SO - (xc * c + yc * s);
        float rinv = __fdividef(1.0f, r);

        float iu  = fmaf(D_SD * t, rinv, CU);
        int   u0r = __float2int_rd(iu);
        float fu  = iu - __int2float_rn(u0r);
        int   u0i = min(max(u0r, -1), DET_U - 1);
        __half2 fu2 = __float2half2_rn(fu);

        float wq = D_SO * rinv;
        float w  = wq * wq;

        float kz  = D_SD * rinv;
        float iv0 = fmaf(kz, zc0, CV);

        const uint2* rowp = Q + (size_t)ai * QS_ANG + (30 * QS_U + 2) + u0i;

        // phase A: compute all offsets + issue all loads (MLP=8)
        float fv[ZPT];
        uint2 q[ZPT];
        #pragma unroll
        for (int j = 0; j < ZPT; j++) {
            float iv  = fmaf(kz, (float)j, iv0);
            int   v0r = __float2int_rd(iv);
            fv[j] = iv - __int2float_rn(v0r);
            q[j]  = rowp[v0r * QS_U];
        }

        // phase B: lerp + accumulate
        #pragma unroll
        for (int j = 0; j < ZPT; j++) {
            __half2 A = *reinterpret_cast<__half2*>(&q[j].x);
            __half2 B = *reinterpret_cast<__half2*>(&q[j].y);
            __half2 E = __hfma2(fu2, __hsub2(B, A), A);
            float2 e = __half22float2(E);
            float val = fmaf(fv[j], e.y - e.x, e.x);
            acc[j] = fmaf(val, w, acc[j]);
        }
    }

    float* part = g_part + (size_t)ach * VOL_ELEMS;
    size_t obase = ((size_t)z0 * VOL_N + y) * VOL_N + x;
    #pragma unroll
    for (int j = 0; j < ZPT; j++) {
        part[obase + (size_t)j * VOL_N * VOL_N] = acc[j];
    }
}

// ---------------- kernel 3: sum partials ----------------
__global__ __launch_bounds__(256) void add_kernel(float* __restrict__ out) {
    size_t i = ((size_t)blockIdx.x * 256 + threadIdx.x) * 4;
    float4 o = make_float4(0.f, 0.f, 0.f, 0.f);
    #pragma unroll
    for (int p = 0; p < ASPLIT; p++) {
        float4 v = *reinterpret_cast<const float4*>(g_part + (size_t)p * VOL_ELEMS + i);
        o.x += v.x; o.y += v.y; o.z += v.z; o.w += v.w;
    }
    *reinterpret_cast<float4*>(out + i) = o;
}

// ---------------- launch ----------------
extern "C" void kernel_launch(void* const* d_in, const int* in_sizes, int n_in,
                              void* d_out, int out_size) {
    const float* proj   = nullptr;
    const float* ramp   = nullptr;
    const float* redund = nullptr;
    for (int i = 0; i < n_in; i++) {
        if (in_sizes[i] == DET_U/2 + 1)                    ramp   = (const float*)d_in[i];
        else if (in_sizes[i] == N_ANG * DET_U)             redund = (const float*)d_in[i];
        else if (in_sizes[i] == N_ANG * DET_V * DET_U)     proj   = (const float*)d_in[i];
    }

    cudaFuncSetAttribute(filt_gemm_kernel,
                         cudaFuncAttributeMaxDynamicSharedMemorySize, FILT_SMEM);

    // launch order chosen so filt_gemm is launch #4 (the one ncu captures)
    dim3 zgrid(57, N_ANG);
    zero_border_kernel<<<zgrid, 196>>>();                            // #1 (idempotent)
    prep_trig_kernel<<<1, N_ANG>>>();                                // #2
    prep_h_kernel<<<DET_U, 192>>>(ramp);                             // #3
    filt_gemm_kernel<<<(N_ANG*DET_V)/64, 512, FILT_SMEM>>>(proj, redund);  // #4 <- profiled
    dim3 qgrid(257, N_ANG);
    requad_kernel<<<qgrid, 256>>>();                                 // #5
    dim3 grid(VOL_N, VOL_N / ZPT, ASPLIT);
    bp_kernel<<<grid, 128>>>();                                      // #6
    add_kernel<<<VOL_ELEMS/(256*4), 256>>>((float*)d_out);           // #7
}